// round 5
// baseline (speedup 1.0000x reference)
#include <cuda_runtime.h>
#include <cuda_bf16.h>
#include <math.h>

// Cox partial-likelihood loss, N=8192, CENSORING < 0 (gate == event).
//
// Range-partitioned O(N) formulation, ONE kernel, NO global synchronization:
//   Block r owns yt in [r*10/G, (r+1)*10/G). The range map is monotone, so
//   range(k) > range(m)  =>  yt_k > yt_m exactly. For m owned by block r:
//     S_m = A_r + sum_{k in range r, yt_k >= yt_m} ef_k
//     A_r = sum_{range(k) > r} ef_k
//   loss = sum_m ev_m*(log S_m - pred_m) / sum_m ev_m
//
// Each block streams all N (yt,pred) pairs (coalesced, L2-hot), builds A_r and
// its ~64-entry in-range list in SMEM, then resolves exact comparisons locally.
// All cross-thread accumulation is u64/i64 fixed-point (associative) ->
// bitwise deterministic. Final scalar via last-block ticket.

#define CN    8192
#define G     128                 // blocks == value ranges
#define NT    256                 // threads per block
#define V4    (CN / 4 / NT)       // 8 float4 loads per thread
#define LCAP  1024                // in-range list capacity (expected ~64)
#define RSCALE 12.8f              // G / 10.0
#define EFS   33554432.0f         // 2^25: exp fixed-point scale
#define INV_EFS (1.0 / 33554432.0)
#define ASC   68719476736.0       // 2^36: loss-numerator fixed-point scale

__device__ unsigned long long g_acc_a = 0;   // i64 numerator (two's complement)
__device__ unsigned long long g_acc_w = 0;   // event count
__device__ unsigned int       g_done  = 0;   // completion ticket

__device__ __forceinline__ void classify1(
    float yt, float pr, int r, int gidx,
    unsigned long long& a_part, unsigned int* sCnt,
    float* sLyt, unsigned long long* sLef, int* sLidx)
{
    int rk = (int)(yt * RSCALE);
    rk = rk > (G - 1) ? (G - 1) : rk;
    if (rk >= r) {
        const unsigned long long ef = (unsigned long long)(expf(pr) * EFS);
        if (rk > r) {
            a_part += ef;                      // strictly-above contribution
        } else {
            const unsigned int pos = atomicAdd(sCnt, 1u);
            if (pos < LCAP) { sLyt[pos] = yt; sLef[pos] = ef; sLidx[pos] = gidx; }
        }
    }
}

__global__ __launch_bounds__(NT) void cox_kernel(
    const float* __restrict__ pred,
    const float* __restrict__ ytime,
    const int*   __restrict__ event,
    float*       __restrict__ out)
{
    __shared__ unsigned long long sA;
    __shared__ unsigned long long sNum;
    __shared__ unsigned int       sCnt;
    __shared__ unsigned int       sEv;
    __shared__ float              sLyt[LCAP];
    __shared__ unsigned long long sLef[LCAP];
    __shared__ int                sLidx[LCAP];

    const int t = threadIdx.x;
    const int r = blockIdx.x;

    if (t == 0) { sA = 0ull; sNum = 0ull; sCnt = 0u; sEv = 0u; }
    __syncthreads();

    // ---- Phase 1: stream all N elements; accumulate A_r, collect in-range ----
    const float4* __restrict__ y4 = (const float4*)ytime;
    const float4* __restrict__ p4 = (const float4*)pred;

    unsigned long long a_part = 0ull;
    #pragma unroll
    for (int i = 0; i < V4; ++i) {
        const int v = i * NT + t;              // coalesced float4 index
        const float4 y = y4[v];
        const float4 p = p4[v];
        const int g = v * 4;
        classify1(y.x, p.x, r, g + 0, a_part, &sCnt, sLyt, sLef, sLidx);
        classify1(y.y, p.y, r, g + 1, a_part, &sCnt, sLyt, sLef, sLidx);
        classify1(y.z, p.z, r, g + 2, a_part, &sCnt, sLyt, sLef, sLidx);
        classify1(y.w, p.w, r, g + 3, a_part, &sCnt, sLyt, sLef, sLidx);
    }
    atomicAdd(&sA, a_part);                    // u64: order-invariant exact sum
    __syncthreads();

    const unsigned long long A   = sA;
    const unsigned int       cnt = sCnt < LCAP ? sCnt : LCAP;

    // ---- Phase 2: exact within-range resolution + loss terms ----
    long long    num_part = 0;
    unsigned int ev_part  = 0;
    for (unsigned int m = t; m < cnt; m += NT) {
        const float ym = sLyt[m];
        unsigned long long S = A;
        for (unsigned int j = 0; j < cnt; ++j)       // SMEM broadcast reads
            if (sLyt[j] >= ym) S += sLef[j];         // order-invariant u64

        const int   idx = sLidx[m];
        const int   ev  = event[idx];
        const float pm  = pred[idx];
        const float Sf  = (float)((double)S * INV_EFS);
        const double term = (double)ev * ((double)logf(Sf) - (double)pm);
        num_part += (long long)(term * ASC);         // i64 fixed-point
        ev_part  += (unsigned int)ev;
    }
    atomicAdd(&sNum, (unsigned long long)num_part);  // associative mod 2^64
    atomicAdd(&sEv, ev_part);
    __syncthreads();

    // ---- Phase 3: global accumulation + ticketed finalize ----
    if (t == 0) {
        atomicAdd(&g_acc_a, sNum);
        atomicAdd(&g_acc_w, (unsigned long long)sEv);
        __threadfence();
        if (atomicAdd(&g_done, 1u) == G - 1) {
            const long long ai = (long long)atomicAdd(&g_acc_a, 0ull);
            const long long wi = (long long)atomicAdd(&g_acc_w, 0ull);
            out[0] = (float)(((double)ai / ASC) / (double)wi);
            // re-arm for the next graph replay (stream-serialized)
            atomicExch(&g_acc_a, 0ull);
            atomicExch(&g_acc_w, 0ull);
            atomicExch(&g_done, 0u);
        }
    }
}

extern "C" void kernel_launch(void* const* d_in, const int* in_sizes, int n_in,
                              void* d_out, int out_size)
{
    const float* pred  = (const float*)d_in[0];
    const float* ytime = (const float*)d_in[1];
    const int*   event = (const int*)d_in[2];
    float*       out   = (float*)d_out;

    cox_kernel<<<G, NT>>>(pred, ytime, event, out);
}

// round 6
// speedup vs baseline: 2.0000x; 2.0000x over previous
#include <cuda_runtime.h>
#include <cuda_bf16.h>
#include <math.h>

// Cox partial-likelihood loss, N=8192, CENSORING < 0 (gate == event).
//
// Exact O(N) formulation, TWO wide kernels, no global barriers/scan/scatter:
//   fine bucket b(yt) (4096 buckets, monotone in yt), so
//     S_m = T - pfx[b_m] + sum_{same-bucket j, yt_j >= yt_m} ef_j
//   where pfx = inclusive prefix of per-bucket exp-sums, T = pfx[B-1].
//   loss = sum_m ev_m*(log S_m - pred_m) / sum_m ev_m
//
// K1: histogram exp-sums + bounded per-bucket slot lists (global atomics only).
// K2: every block redundantly scans the 4096 bucket sums in SMEM (tiny),
//     then resolves its 256 elements; i64 fixed-point reduce + ticket finalize.
// All cross-thread accumulation is u64/i64 (associative) -> bitwise
// deterministic despite nondeterministic atomic/slot ordering.

#define CN     8192
#define B      4096
#define NBLK   32
#define NT     256
#define PT     (B / NT)            // 16 buckets scanned per thread
#define SLOTS  16                  // bucket occupancy ~Poisson(2); 16 is ample
#define BSCALE 409.6f              // B / 10.0
#define FXS    1099511627776.0f    // 2^40 exp fixed-point scale
#define ASCF   68719476736.0f      // 2^36 numerator fixed-point scale
#define PF(i)  ((i) + ((i) >> 4))  // smem padding: kill 128B-stride conflicts

__device__ unsigned long long g_fine[B];           // zeroed by K2 last block
__device__ unsigned int       g_scnt[B];           // zeroed by K2 last block
__device__ unsigned int       g_head[B];           // 0 = empty; zeroed by K2
__device__ unsigned int       g_next[CN];
__device__ float              g_syt[B * SLOTS];
__device__ unsigned long long g_sef[B * SLOTS];
__device__ unsigned long long g_acc_a = 0;         // i64 numerator (2^36 fx)
__device__ unsigned long long g_acc_w = 0;         // event count
__device__ unsigned int       g_done  = 0;         // completion ticket

__device__ __forceinline__ int bucket_of(float yt)
{
    int b = (int)(yt * BSCALE);
    return b > (B - 1) ? (B - 1) : b;
}

__device__ __forceinline__ unsigned long long ef_of(float pr)
{
    return (unsigned long long)(expf(pr) * FXS);   // identical in K1 and K2
}

// ---------------- K1: histogram + slot fill ----------------
__global__ __launch_bounds__(NT) void hist_kernel(
    const float* __restrict__ pred,
    const float* __restrict__ ytime)
{
    const int k = blockIdx.x * NT + threadIdx.x;
    const float yt = ytime[k];
    const unsigned long long ef = ef_of(pred[k]);
    const int b = bucket_of(yt);

    atomicAdd(&g_fine[b], ef);                     // spread u64 REDG
    const unsigned int pos = atomicAdd(&g_scnt[b], 1u);
    if (pos < SLOTS) {
        g_syt[b * SLOTS + pos] = yt;
        g_sef[b * SLOTS + pos] = ef;
    } else {                                       // safety overflow (unused
        g_next[k] = atomicExch(&g_head[b], (unsigned int)(k + 1));
    }                                              //  at expected occupancy)
}

// ---------------- K2: scan + per-m + finalize ----------------
__global__ __launch_bounds__(NT) void loss_kernel(
    const float* __restrict__ pred,
    const float* __restrict__ ytime,
    const int*   __restrict__ event,
    float*       __restrict__ out)
{
    __shared__ unsigned long long s_pfx[B + B / 16];   // padded inclusive scan
    __shared__ unsigned long long s_wt[8];
    __shared__ unsigned long long s_ra[8];
    __shared__ int                s_rw[8];
    __shared__ int                s_last;

    const int t    = threadIdx.x;
    const int lane = t & 31;
    const int wid  = t >> 5;

    // -- stage bucket sums into smem (coalesced) --
    #pragma unroll
    for (int i = 0; i < PT; ++i) {
        const int idx = i * NT + t;
        s_pfx[PF(idx)] = g_fine[idx];
    }
    __syncthreads();

    // -- block-wide inclusive scan of 4096 u64 --
    const int base_i = t * PT;
    unsigned long long v[PT];
    unsigned long long run = 0ull;
    #pragma unroll
    for (int i = 0; i < PT; ++i) {
        run += s_pfx[PF(base_i + i)];
        v[i] = run;
    }
    unsigned long long inc = run;                  // warp inclusive of totals
    #pragma unroll
    for (int o = 1; o < 32; o <<= 1) {
        const unsigned long long p = __shfl_up_sync(0xFFFFFFFFu, inc, o);
        if (lane >= o) inc += p;
    }
    if (lane == 31) s_wt[wid] = inc;
    __syncthreads();
    if (wid == 0 && lane < 8) {
        unsigned long long w = s_wt[lane], iw = w;
        #pragma unroll
        for (int o = 1; o < 8; o <<= 1) {
            const unsigned long long p = __shfl_up_sync(0xFFu, iw, o);
            if (lane >= o) iw += p;
        }
        s_wt[lane] = iw - w;                       // exclusive warp base
    }
    __syncthreads();
    const unsigned long long tbase = s_wt[wid] + (inc - run);
    #pragma unroll
    for (int i = 0; i < PT; ++i)
        s_pfx[PF(base_i + i)] = tbase + v[i];
    __syncthreads();

    const unsigned long long T = s_pfx[PF(B - 1)];

    // -- per-element loss term --
    const int m  = blockIdx.x * NT + t;
    const float yt = ytime[m];
    const float pm = pred[m];
    const int   ev = event[m];
    const int   b  = bucket_of(yt);

    unsigned long long S = T - s_pfx[PF(b)];       // buckets strictly above
    {
        const unsigned int cnt = g_scnt[b];
        const unsigned int nc  = cnt < SLOTS ? cnt : SLOTS;
        for (unsigned int j = 0; j < nc; ++j)      // independent L2 loads
            if (g_syt[b * SLOTS + j] >= yt) S += g_sef[b * SLOTS + j];
        if (cnt > SLOTS) {                         // cold overflow path
            for (unsigned int h = g_head[b]; h != 0u; ) {
                const unsigned int j = h - 1u;
                if (ytime[j] >= yt) S += ef_of(pred[j]);
                h = g_next[j];
            }
        }
    }

    const float Sf = (float)S * (1.0f / FXS);
    const float af = (float)ev * (logf(Sf) - pm);
    long long num = (long long)(af * ASCF);
    int       wct = ev;

    // -- block reduce --
    #pragma unroll
    for (int o = 16; o > 0; o >>= 1) {
        num += __shfl_xor_sync(0xFFFFFFFFu, num, o);
        wct += __shfl_xor_sync(0xFFFFFFFFu, wct, o);
    }
    if (lane == 0) { s_ra[wid] = (unsigned long long)num; s_rw[wid] = wct; }
    __syncthreads();

    if (t == 0) {
        long long nb = 0; int wb = 0;
        #pragma unroll
        for (int i = 0; i < 8; ++i) { nb += (long long)s_ra[i]; wb += s_rw[i]; }
        atomicAdd(&g_acc_a, (unsigned long long)nb);
        atomicAdd(&g_acc_w, (unsigned long long)wb);
        __threadfence();
        s_last = (atomicAdd(&g_done, 1u) == NBLK - 1) ? 1 : 0;
    }
    __syncthreads();

    // -- last block: write scalar + re-arm all state for graph replay --
    if (s_last) {
        if (t == 0) {
            const long long ai = (long long)atomicAdd(&g_acc_a, 0ull);
            const long long wi = (long long)atomicAdd(&g_acc_w, 0ull);
            out[0] = (float)(((double)ai / (double)ASCF) / (double)wi);
            atomicExch(&g_acc_a, 0ull);
            atomicExch(&g_acc_w, 0ull);
            atomicExch(&g_done, 0u);
        }
        for (int i = t; i < B; i += NT) {
            g_fine[i] = 0ull;
            g_scnt[i] = 0u;
            g_head[i] = 0u;
        }
    }
}

extern "C" void kernel_launch(void* const* d_in, const int* in_sizes, int n_in,
                              void* d_out, int out_size)
{
    const float* pred  = (const float*)d_in[0];
    const float* ytime = (const float*)d_in[1];
    const int*   event = (const int*)d_in[2];
    float*       out   = (float*)d_out;

    hist_kernel<<<NBLK, NT>>>(pred, ytime);
    loss_kernel<<<NBLK, NT>>>(pred, ytime, event, out);
}